// round 1
// baseline (speedup 1.0000x reference)
#include <cuda_runtime.h>
#include <math.h>

// Problem constants
#define Bn 16
#define Tn 28
#define Hn 32
#define Wn 32
#define HW 1024
#define Fh 64
#define NIMG (Bn * Tn)   // 448

// ---------------- device scratch (no allocations allowed) ----------------
__device__ float g_xg[(size_t)NIMG * HW * 192];   // 352 MB, reused per direction pass
__device__ float g_x0[(size_t)NIMG * HW * 128];   // layer-0 bidir output
__device__ float g_y1[(size_t)NIMG * HW * 128];   // layer-1 bidir output
__device__ float g_h  [Bn * HW * Fh];             // current hidden state
__device__ float g_z  [Bn * HW * Fh];             // z gate
__device__ float g_rh [Bn * HW * Fh];             // r*h
__device__ float g_gh [Bn * HW * 2 * Fh];         // conv(h, wh_zr)
__device__ float g_gh2[Bn * HW * Fh];             // conv(r*h, wh_h)

// ---------------- packed f32x2 helpers (FFMA2 path) ----------------
__device__ __forceinline__ unsigned long long pack2(float v) {
    unsigned long long r;
    asm("mov.b64 %0, {%1, %1};" : "=l"(r) : "f"(v));
    return r;
}
__device__ __forceinline__ void ffma2(unsigned long long& d, unsigned long long a,
                                      unsigned long long b) {
    asm("fma.rn.f32x2 %0, %1, %2, %0;" : "+l"(d) : "l"(a), "l"(b));
}
__device__ __forceinline__ void unpack2(unsigned long long a, float& lo, float& hi) {
    asm("mov.b64 {%0, %1}, %2;" : "=f"(lo), "=f"(hi) : "l"(a));
}

// Shared-memory accumulate: 16x16 pixel tile, 32 couts/thread, one cin chunk of 16.
// s_in layout: [ci][18*18] with plane stride 325 (conflict-free reads, px stride 1)
// s_w  layout: [k][ci][32] (cout-contiguous -> float4 broadcast loads)
__device__ __forceinline__ void accum_chunk(const float* __restrict__ s_in,
                                            const float* __restrict__ s_w,
                                            int px, int py,
                                            unsigned long long acc[16]) {
#pragma unroll
    for (int k = 0; k < 9; k++) {
        const int ky = k / 3, kx = k % 3;
        const int ibase = (py + ky) * 18 + (px + kx);
#pragma unroll
        for (int ci = 0; ci < 16; ci++) {
            float v = s_in[ci * 325 + ibase];
            unsigned long long v2 = pack2(v);
            const float* wr = &s_w[(k * 16 + ci) * 32];
#pragma unroll
            for (int j = 0; j < 8; j++) {
                ulonglong2 wv = *(const ulonglong2*)(wr + j * 4);
                ffma2(acc[2 * j],     v2, wv.x);
                ffma2(acc[2 * j + 1], v2, wv.y);
            }
        }
    }
}

// ---------------- generic 3x3 SAME conv, NHWC fp32 ----------------
// grid: (4 tiles of 16x16, n_img, cout_groups_of_32)
// w layout: [3][3][cin][wcs] ; couts taken at  wco + cg*32 + co
// out layout: [img][HW][ocs] ; written at oco + cg*32 + co
__global__ void __launch_bounds__(256)
conv3x3(const float* __restrict__ in, int cin,
        const float* __restrict__ w, int wcs, int wco,
        const float* __restrict__ bias,
        float* __restrict__ out, int ocs, int oco)
{
    __shared__ __align__(16) float s_in[16 * 325];
    __shared__ __align__(16) float s_w[9 * 16 * 32];

    const int tid = threadIdx.x;
    const int px = tid & 15, py = tid >> 4;
    const int tx0 = (blockIdx.x & 1) * 16, ty0 = (blockIdx.x >> 1) * 16;
    const int img = blockIdx.y;
    const int cg  = blockIdx.z;

    const float* inb = in + (size_t)img * HW * cin;

    unsigned long long acc[16];
#pragma unroll
    for (int i = 0; i < 16; i++) acc[i] = 0ull;

    const int nchunk = (cin + 15) >> 4;
    for (int ch = 0; ch < nchunk; ch++) {
        const int cc = ch * 16;
        __syncthreads();
        // stage input tile 18x18 x 16 cins (zero-padded at borders / cin tail)
        for (int idx = tid; idx < 18 * 18 * 16; idx += 256) {
            const int ci  = idx & 15;
            const int pix = idx >> 4;
            const int rx = pix % 18, ry = pix / 18;
            const int gy = ty0 + ry - 1, gx = tx0 + rx - 1;
            const int c = cc + ci;
            float v = 0.f;
            if (gy >= 0 && gy < Hn && gx >= 0 && gx < Wn && c < cin)
                v = inb[((size_t)gy * Wn + gx) * cin + c];
            s_in[ci * 325 + ry * 18 + rx] = v;
        }
        // stage weights 9 x 16 x 32
        for (int idx = tid; idx < 9 * 16 * 32; idx += 256) {
            const int co = idx & 31;
            const int ci = (idx >> 5) & 15;
            const int k  = idx >> 9;
            const int c  = cc + ci;
            float v = 0.f;
            if (c < cin)
                v = w[((size_t)k * cin + c) * wcs + wco + cg * 32 + co];
            s_w[idx] = v;
        }
        __syncthreads();
        accum_chunk(s_in, s_w, px, py, acc);
    }

    float res[32];
#pragma unroll
    for (int i = 0; i < 16; i++) unpack2(acc[i], res[2 * i], res[2 * i + 1]);
    if (bias) {
#pragma unroll
        for (int i = 0; i < 32; i++) res[i] += bias[cg * 32 + i];
    }
    const size_t obase =
        ((size_t)img * HW + (size_t)(ty0 + py) * Wn + (tx0 + px)) * ocs + oco + cg * 32;
#pragma unroll
    for (int i = 0; i < 8; i++) {
        float4 v = make_float4(res[4 * i], res[4 * i + 1], res[4 * i + 2], res[4 * i + 3]);
        *(float4*)(out + obase + 4 * i) = v;
    }
}

// ---------------- GRU elementwise kernels ----------------
__global__ void __launch_bounds__(256)
gru_e1(const float* __restrict__ xg, const float* __restrict__ gh,
       const float* __restrict__ h, float* __restrict__ z,
       float* __restrict__ rh, int t)
{
    const int idx = blockIdx.x * 256 + threadIdx.x;
    if (idx >= Bn * HW * Fh) return;
    const int c = idx & 63;
    const int p = (idx >> 6) & 1023;
    const int b = idx >> 16;
    const size_t xbase = (((size_t)(b * Tn + t) * HW) + p) * 192;
    const size_t gbase = ((size_t)b * HW + p) * 128;
    const float zz = 1.f / (1.f + expf(-(xg[xbase + c]      + gh[gbase + c])));
    const float rr = 1.f / (1.f + expf(-(xg[xbase + 64 + c] + gh[gbase + 64 + c])));
    z[idx]  = zz;
    rh[idx] = rr * h[idx];
}

__global__ void __launch_bounds__(256)
gru_e2(const float* __restrict__ xg, const float* __restrict__ gh2,
       const float* __restrict__ z, float* __restrict__ h,
       float* __restrict__ y, int t, int ocs, int oco)
{
    const int idx = blockIdx.x * 256 + threadIdx.x;
    if (idx >= Bn * HW * Fh) return;
    const int c = idx & 63;
    const int p = (idx >> 6) & 1023;
    const int b = idx >> 16;
    const size_t xbase = (((size_t)(b * Tn + t) * HW) + p) * 192;
    const float hh = tanhf(xg[xbase + 128 + c] + gh2[idx]);
    const float zz = z[idx];
    const float hn = zz * h[idx] + (1.f - zz) * hh;
    h[idx] = hn;
    y[(((size_t)(b * Tn + t) * HW) + p) * ocs + oco + c] = hn;
}

// ---------------- fused head: 3x3 conv (256->32) + 1x1 (32->1) + ReLU ----------------
// xc[c] = (c<128) ? x0[c]+y1[c] : x0[c-128]  -- never materialized
__global__ void __launch_bounds__(256)
final_conv(const float* __restrict__ x0, const float* __restrict__ y1,
           const float* __restrict__ wc, const float* __restrict__ bc,
           const float* __restrict__ wo, const float* __restrict__ bo,
           float* __restrict__ out)
{
    __shared__ __align__(16) float s_in[16 * 325];
    __shared__ __align__(16) float s_w[9 * 16 * 32];

    const int tid = threadIdx.x;
    const int px = tid & 15, py = tid >> 4;
    const int tx0 = (blockIdx.x & 1) * 16, ty0 = (blockIdx.x >> 1) * 16;
    const int img = blockIdx.y;

    const float* x0b = x0 + (size_t)img * HW * 128;
    const float* y1b = y1 + (size_t)img * HW * 128;

    unsigned long long acc[16];
#pragma unroll
    for (int i = 0; i < 16; i++) acc[i] = 0ull;

    for (int ch = 0; ch < 16; ch++) {
        const int cc = ch * 16;
        __syncthreads();
        for (int idx = tid; idx < 18 * 18 * 16; idx += 256) {
            const int ci  = idx & 15;
            const int pix = idx >> 4;
            const int rx = pix % 18, ry = pix / 18;
            const int gy = ty0 + ry - 1, gx = tx0 + rx - 1;
            float v = 0.f;
            if (gy >= 0 && gy < Hn && gx >= 0 && gx < Wn) {
                const int c = cc + ci;
                const size_t pbase = ((size_t)gy * Wn + gx) * 128;
                v = (c < 128) ? (x0b[pbase + c] + y1b[pbase + c]) : x0b[pbase + c - 128];
            }
            s_in[ci * 325 + ry * 18 + rx] = v;
        }
        for (int idx = tid; idx < 9 * 16 * 32; idx += 256) {
            const int co = idx & 31;
            const int ci = (idx >> 5) & 15;
            const int k  = idx >> 9;
            s_w[idx] = wc[((size_t)k * 256 + cc + ci) * 32 + co];
        }
        __syncthreads();
        accum_chunk(s_in, s_w, px, py, acc);
    }

    float res[32];
#pragma unroll
    for (int i = 0; i < 16; i++) unpack2(acc[i], res[2 * i], res[2 * i + 1]);

    float o = bo[0];
#pragma unroll
    for (int i = 0; i < 32; i++) o += (res[i] + bc[i]) * wo[i];
    o = fmaxf(o, 0.f);
    out[(size_t)img * HW + (size_t)(ty0 + py) * Wn + (tx0 + px)] = o;
}

// ---------------- host orchestration ----------------
static void run_dir(const float* in, int cin, const float* wx, const float* wh,
                    const float* bias, float* xg, float* h, float* z, float* rh,
                    float* gh, float* gh2, float* yout, int ooff, bool rev)
{
    // 1) xg = conv3x3(in, wx) + bias over all T frames (cout = 192)
    conv3x3<<<dim3(4, NIMG, 6), 256>>>(in, cin, wx, 192, 0, bias, xg, 192, 0);
    // 2) h = 0
    cudaMemsetAsync(h, 0, (size_t)Bn * HW * Fh * sizeof(float));
    // 3) sequential scan
    for (int s = 0; s < Tn; s++) {
        const int t = rev ? (Tn - 1 - s) : s;
        // gh = conv3x3(h, wh_zr)  -> 128 couts
        conv3x3<<<dim3(4, Bn, 4), 256>>>(h, Fh, wh, 192, 0, nullptr, gh, 128, 0);
        gru_e1<<<4096, 256>>>(xg, gh, h, z, rh, t);
        // gh2 = conv3x3(r*h, wh_h) -> 64 couts (weight cout offset 128)
        conv3x3<<<dim3(4, Bn, 2), 256>>>(rh, Fh, wh, 192, 128, nullptr, gh2, 64, 0);
        gru_e2<<<4096, 256>>>(xg, gh2, z, h, yout, t, 128, ooff);
    }
}

extern "C" void kernel_launch(void* const* d_in, const int* in_sizes, int n_in,
                              void* d_out, int out_size)
{
    const float* x       = (const float*)d_in[0];
    const float* wx_f0   = (const float*)d_in[1];
    const float* wh_f0   = (const float*)d_in[2];
    const float* b_f0    = (const float*)d_in[3];
    const float* wx_b0   = (const float*)d_in[4];
    const float* wh_b0   = (const float*)d_in[5];
    const float* b_b0    = (const float*)d_in[6];
    const float* wx_f1   = (const float*)d_in[7];
    const float* wh_f1   = (const float*)d_in[8];
    const float* b_f1    = (const float*)d_in[9];
    const float* wx_b1   = (const float*)d_in[10];
    const float* wh_b1   = (const float*)d_in[11];
    const float* b_b1    = (const float*)d_in[12];
    const float* w_conv1 = (const float*)d_in[13];
    const float* b_conv1 = (const float*)d_in[14];
    const float* w_out   = (const float*)d_in[15];
    const float* b_out   = (const float*)d_in[16];
    float* out = (float*)d_out;

    float *xg, *x0, *y1, *h, *z, *rh, *gh, *gh2;
    cudaGetSymbolAddress((void**)&xg,  g_xg);
    cudaGetSymbolAddress((void**)&x0,  g_x0);
    cudaGetSymbolAddress((void**)&y1,  g_y1);
    cudaGetSymbolAddress((void**)&h,   g_h);
    cudaGetSymbolAddress((void**)&z,   g_z);
    cudaGetSymbolAddress((void**)&rh,  g_rh);
    cudaGetSymbolAddress((void**)&gh,  g_gh);
    cudaGetSymbolAddress((void**)&gh2, g_gh2);

    // Layer 0: bidirectional over raw input (cin=24) -> x0 (128 ch)
    run_dir(x,  24,  wx_f0, wh_f0, b_f0, xg, h, z, rh, gh, gh2, x0, 0,  false);
    run_dir(x,  24,  wx_b0, wh_b0, b_b0, xg, h, z, rh, gh, gh2, x0, 64, true);
    // Layer 1: bidirectional over x0 (cin=128) -> y1 (128 ch)
    run_dir(x0, 128, wx_f1, wh_f1, b_f1, xg, h, z, rh, gh, gh2, y1, 0,  false);
    run_dir(x0, 128, wx_b1, wh_b1, b_b1, xg, h, z, rh, gh, gh2, y1, 64, true);
    // Fused head
    final_conv<<<dim3(4, NIMG), 256>>>(x0, y1, w_conv1, b_conv1, w_out, b_out, out);
}